// round 2
// baseline (speedup 1.0000x reference)
#include <cuda_runtime.h>
#include <cuda_bf16.h>
#include <cstdint>

// Problem constants
#define D_IN   2048   // IN_CH
#define F_MID  1024   // INTER_CH
#define NEXP   32
#define CAP    512
#define TTOK   8192   // B*S

#define BM 64
#define BN 64
#define BK 16

// Scratch (allocation-free rule: __device__ globals)
__device__ int   g_slots[NEXP * CAP];
__device__ int   g_counts[NEXP];
__device__ float g_H[(size_t)NEXP * CAP * F_MID];   // 64 MB intermediate

// ---------------------------------------------------------------------------
// Kernel 1: stable dispatch. Block e scans all tokens in order; pos within
// expert = count of earlier tokens with the same expert (matches jnp.cumsum).
// NOTE: indices are int32 on device (JAX x64 disabled downcasts jnp.int64).
// ---------------------------------------------------------------------------
__global__ void build_slots(const int* __restrict__ idx) {
    const int e   = blockIdx.x;
    const int tid = threadIdx.x;
    const int lane = tid & 31, w = tid >> 5;
    __shared__ int wsum[8];
    int base = 0;
    for (int start = 0; start < TTOK; start += 256) {
        int t = start + tid;
        bool m = (idx[t] == e);
        unsigned bal = __ballot_sync(0xffffffffu, m);
        if (lane == 0) wsum[w] = __popc(bal);
        __syncthreads();
        int woff = 0, tot = 0;
        #pragma unroll
        for (int i = 0; i < 8; i++) { int v = wsum[i]; tot += v; if (i < w) woff += v; }
        if (m) {
            int pos = base + woff + __popc(bal & ((1u << lane) - 1u));
            if (pos < CAP) g_slots[e * CAP + pos] = t;
        }
        base += tot;
        __syncthreads();
    }
    if (tid == 0) g_counts[e] = base < CAP ? base : CAP;
}

// ---------------------------------------------------------------------------
// Kernel 2: fused H = silu(Xg @ W1 + b1) * (Xg @ W3 + b3) per expert.
// A rows gathered via slot->token indirection (no dispatch buffer).
// 64x64x16 tiles, 256 threads, 4x4 per-thread tiles, dual accumulators.
// ---------------------------------------------------------------------------
__global__ __launch_bounds__(256, 2) void gemm13(
    const float* __restrict__ x,
    const float* __restrict__ W1, const float* __restrict__ b1,
    const float* __restrict__ W3, const float* __restrict__ b3)
{
    const int e  = blockIdx.z;
    const int m0 = blockIdx.y * BM;
    const int n0 = blockIdx.x * BN;
    const int count = g_counts[e];
    if (m0 >= count) return;

    __shared__ float As [BK][BM + 4];
    __shared__ float B1s[BK][BN + 4];
    __shared__ float B3s[BK][BN + 4];

    const int tid = threadIdx.x;
    // A loader: thread -> (row a_m, 4 consecutive k at a_k)
    const int a_m = tid >> 2;
    const int a_k = (tid & 3) * 4;
    const int mrow = m0 + a_m;
    const int tok  = (mrow < count) ? g_slots[e * CAP + mrow] : 0;
    const float* a_ptr = x + (size_t)tok * D_IN + a_k;
    // B loader: thread -> (row b_k, 4 consecutive n at b_n)
    const int b_k = tid >> 4;
    const int b_n = (tid & 15) * 4;
    const float* w1_ptr = W1 + ((size_t)e * D_IN + b_k) * F_MID + n0 + b_n;
    const float* w3_ptr = W3 + ((size_t)e * D_IN + b_k) * F_MID + n0 + b_n;

    const int tx = tid & 15, ty = tid >> 4;

    float acc1[4][4] = {}, acc3[4][4] = {};

    float4 ra  = *(const float4*)(a_ptr);
    float4 rb1 = *(const float4*)(w1_ptr);
    float4 rb3 = *(const float4*)(w3_ptr);

    const int KT = D_IN / BK;
    for (int kt = 0; kt < KT; ++kt) {
        As[a_k + 0][a_m] = ra.x;
        As[a_k + 1][a_m] = ra.y;
        As[a_k + 2][a_m] = ra.z;
        As[a_k + 3][a_m] = ra.w;
        *(float4*)&B1s[b_k][b_n] = rb1;
        *(float4*)&B3s[b_k][b_n] = rb3;
        __syncthreads();
        if (kt + 1 < KT) {
            ra  = *(const float4*)(a_ptr + (kt + 1) * BK);
            rb1 = *(const float4*)(w1_ptr + (size_t)(kt + 1) * BK * F_MID);
            rb3 = *(const float4*)(w3_ptr + (size_t)(kt + 1) * BK * F_MID);
        }
        #pragma unroll
        for (int k = 0; k < BK; ++k) {
            float4 av  = *(const float4*)&As [k][ty * 4];
            float4 bv1 = *(const float4*)&B1s[k][tx * 4];
            float4 bv3 = *(const float4*)&B3s[k][tx * 4];
            float a[4]  = {av.x,  av.y,  av.z,  av.w};
            float p[4]  = {bv1.x, bv1.y, bv1.z, bv1.w};
            float q[4]  = {bv3.x, bv3.y, bv3.z, bv3.w};
            #pragma unroll
            for (int i = 0; i < 4; ++i)
                #pragma unroll
                for (int j = 0; j < 4; ++j) {
                    acc1[i][j] += a[i] * p[j];
                    acc3[i][j] += a[i] * q[j];
                }
        }
        __syncthreads();
    }

    // Epilogue: SwiGLU, store rows < count to g_H
    const int gn = n0 + tx * 4;
    float bb1[4], bb3[4];
    #pragma unroll
    for (int j = 0; j < 4; ++j) {
        bb1[j] = b1[(size_t)e * F_MID + gn + j];
        bb3[j] = b3[(size_t)e * F_MID + gn + j];
    }
    #pragma unroll
    for (int i = 0; i < 4; ++i) {
        int gm = m0 + ty * 4 + i;
        if (gm < count) {
            float* Hrow = g_H + ((size_t)e * CAP + gm) * F_MID + gn;
            #pragma unroll
            for (int j = 0; j < 4; ++j) {
                float z1 = acc1[i][j] + bb1[j];
                float z3 = acc3[i][j] + bb3[j];
                float s  = z1 / (1.0f + __expf(-z1));   // silu
                Hrow[j]  = s * z3;
            }
        }
    }
}

// ---------------------------------------------------------------------------
// Kernel 3: out[token] = H @ W2 + b2, scatter epilogue to original positions.
// ---------------------------------------------------------------------------
__global__ __launch_bounds__(256, 2) void gemm2k(
    const float* __restrict__ W2, const float* __restrict__ b2,
    float* __restrict__ out)
{
    const int e  = blockIdx.z;
    const int m0 = blockIdx.y * BM;
    const int n0 = blockIdx.x * BN;
    const int count = g_counts[e];
    if (m0 >= count) return;

    __shared__ float As[BK][BM + 4];
    __shared__ float Bs[BK][BN + 4];

    const int tid = threadIdx.x;
    const int a_m = tid >> 2;
    const int a_k = (tid & 3) * 4;
    const float* a_ptr = g_H + ((size_t)e * CAP + m0 + a_m) * F_MID + a_k;
    const int b_k = tid >> 4;
    const int b_n = (tid & 15) * 4;
    const float* w2_ptr = W2 + ((size_t)e * F_MID + b_k) * D_IN + n0 + b_n;

    const int tx = tid & 15, ty = tid >> 4;

    float acc[4][4] = {};

    float4 ra = *(const float4*)(a_ptr);
    float4 rb = *(const float4*)(w2_ptr);

    const int KT = F_MID / BK;
    for (int kt = 0; kt < KT; ++kt) {
        As[a_k + 0][a_m] = ra.x;
        As[a_k + 1][a_m] = ra.y;
        As[a_k + 2][a_m] = ra.z;
        As[a_k + 3][a_m] = ra.w;
        *(float4*)&Bs[b_k][b_n] = rb;
        __syncthreads();
        if (kt + 1 < KT) {
            ra = *(const float4*)(a_ptr + (kt + 1) * BK);
            rb = *(const float4*)(w2_ptr + (size_t)(kt + 1) * BK * D_IN);
        }
        #pragma unroll
        for (int k = 0; k < BK; ++k) {
            float4 av = *(const float4*)&As[k][ty * 4];
            float4 bv = *(const float4*)&Bs[k][tx * 4];
            float a[4] = {av.x, av.y, av.z, av.w};
            float b[4] = {bv.x, bv.y, bv.z, bv.w};
            #pragma unroll
            for (int i = 0; i < 4; ++i)
                #pragma unroll
                for (int j = 0; j < 4; ++j)
                    acc[i][j] += a[i] * b[j];
        }
        __syncthreads();
    }

    const int gn = n0 + tx * 4;
    float bb[4];
    #pragma unroll
    for (int j = 0; j < 4; ++j) bb[j] = b2[(size_t)e * D_IN + gn + j];
    #pragma unroll
    for (int i = 0; i < 4; ++i) {
        int gm = m0 + ty * 4 + i;
        if (gm < count) {
            int tok = g_slots[e * CAP + gm];
            float* orow = out + (size_t)tok * D_IN + gn;
            #pragma unroll
            for (int j = 0; j < 4; ++j) orow[j] = acc[i][j] + bb[j];
        }
    }
}

// ---------------------------------------------------------------------------
extern "C" void kernel_launch(void* const* d_in, const int* in_sizes, int n_in,
                              void* d_out, int out_size) {
    const float* x   = (const float*)d_in[0];
    const float* W1  = (const float*)d_in[1];
    const float* b1  = (const float*)d_in[2];
    const float* W2  = (const float*)d_in[3];
    const float* b2  = (const float*)d_in[4];
    const float* W3  = (const float*)d_in[5];
    const float* b3  = (const float*)d_in[6];
    const int*   idx = (const int*)d_in[7];   // int64 in reference, int32 on device (JAX x64 off)
    float* out = (float*)d_out;

    build_slots<<<NEXP, 256>>>(idx);

    dim3 g1(F_MID / BN, CAP / BM, NEXP);   // (16, 8, 32)
    gemm13<<<g1, 256>>>(x, W1, b1, W3, b3);

    dim3 g2(D_IN / BN, CAP / BM, NEXP);    // (32, 8, 32)
    gemm2k<<<g2, 256>>>(W2, b2, out);
}

// round 5
// speedup vs baseline: 2.3632x; 2.3632x over previous
#include <cuda_runtime.h>
#include <cstdint>

#define D_IN   2048
#define F_MID  1024
#define NEXP   32
#define CAP    512
#define TTOK   8192

#define SA 20u          // A smem row stride (words)
#define SBW 132u        // B smem row stride (words)

// scratch (__device__ globals: allocation-free rule)
__device__ int   g_slots[NEXP * CAP];
__device__ int   g_counts[NEXP];
__device__ float g_Z1[(size_t)NEXP * CAP * F_MID];  // 64 MB
__device__ float g_H [(size_t)NEXP * CAP * F_MID];  // 64 MB

__device__ __forceinline__ uint32_t f2tf(float f) {
    uint32_t u; asm("cvt.rna.tf32.f32 %0, %1;" : "=r"(u) : "f"(f)); return u;
}
__device__ __forceinline__ void mma8(float* c, const uint32_t* a, const uint32_t* b) {
    asm volatile(
        "mma.sync.aligned.m16n8k8.row.col.f32.tf32.tf32.f32 "
        "{%0,%1,%2,%3}, {%4,%5,%6,%7}, {%8,%9}, {%0,%1,%2,%3};"
        : "+f"(c[0]), "+f"(c[1]), "+f"(c[2]), "+f"(c[3])
        : "r"(a[0]), "r"(a[1]), "r"(a[2]), "r"(a[3]), "r"(b[0]), "r"(b[1]));
}

// ---------------------------------------------------------------- dispatch
__global__ void build_slots(const int* __restrict__ idx) {
    const int e = blockIdx.x, tid = threadIdx.x;
    const int lane = tid & 31, w = tid >> 5;
    __shared__ int wsum[8];
    int base = 0;
    for (int start = 0; start < TTOK; start += 256) {
        int t = start + tid;
        bool m = (idx[t] == e);
        unsigned bal = __ballot_sync(0xffffffffu, m);
        if (lane == 0) wsum[w] = __popc(bal);
        __syncthreads();
        int woff = 0, tot = 0;
        #pragma unroll
        for (int i = 0; i < 8; i++) { int v = wsum[i]; tot += v; if (i < w) woff += v; }
        if (m) {
            int pos = base + woff + __popc(bal & ((1u << lane) - 1u));
            if (pos < CAP) g_slots[e * CAP + pos] = t;
        }
        base += tot;
        __syncthreads();
    }
    if (tid == 0) g_counts[e] = base < CAP ? base : CAP;
}

// ---------------------------------------------------------------- GEMM
// MODE 1: g_Z1 = gatherX @ W1 + b1
// MODE 3: g_H  = silu(g_Z1) * (gatherX @ W3 + b3)
// MODE 2: out[tok] = g_H @ W2 + b2  (scatter)
// CTA 128x128, K-chunk 16, 8 warps (2M x 4N), warp tile 64x32, tf32 mma.
template<int MODE>
__global__ __launch_bounds__(256, 2) void gemm_tc(
    const float* __restrict__ x, const float* __restrict__ W,
    const float* __restrict__ bias, float* __restrict__ out)
{
    constexpr int KD = (MODE == 2) ? F_MID : D_IN;
    constexpr int NW = (MODE == 2) ? D_IN  : F_MID;
    constexpr int NK = KD / 16;

    const int e  = blockIdx.z;
    const int m0 = blockIdx.y * 128;
    const int n0 = blockIdx.x * 128;
    const int count = g_counts[e];
    if (m0 >= count) return;

    __shared__ uint32_t smA[2][128 * SA];   // 2 * 2560 words
    __shared__ uint32_t smB[2][16 * SBW];   // 2 * 2112 words  (total 37376 B)

    const int tid = threadIdx.x, wid = tid >> 5, lane = tid & 31;
    const int wm = wid >> 2, wn = wid & 3;
    const int qg = lane >> 2, qt = lane & 3;

    // A producer: 2 float4 per thread: rows (tid>>2)+{0,64}, cols (tid&3)*4..+3
    const int ar  = tid >> 2;
    const int ak4 = (tid & 3) * 4;
    const float* ap[2];
    uint32_t a_st[2];
    #pragma unroll
    for (int j = 0; j < 2; j++) {
        const int grow = m0 + ar + 64 * j;
        const float* base;
        if (MODE == 2) {
            base = g_H + ((size_t)e * CAP + grow) * F_MID;   // rows>=count: garbage, masked later
        } else {
            const int tok = (grow < count) ? g_slots[e * CAP + grow] : 0;
            base = x + (size_t)tok * D_IN;
        }
        ap[j]   = base + ak4;
        a_st[j] = (uint32_t)(ar + 64 * j) * SA + ak4;
    }
    // B producer: 2 float4 per thread: k-rows (tid>>5)+{0,8}, cols (tid&31)*4..+3
    const int bkr = tid >> 5;
    const int bn4 = (tid & 31) * 4;
    const float* wp = W + ((size_t)e * KD + bkr) * NW + n0 + bn4;
    const uint32_t b_st[2] = { (uint32_t)bkr * SBW + bn4, (uint32_t)(bkr + 8) * SBW + bn4 };

    float4 aR[2], bR[2];
    auto LDG = [&](int kt) {
        #pragma unroll
        for (int j = 0; j < 2; j++) aR[j] = *(const float4*)(ap[j] + kt * 16);
        #pragma unroll
        for (int j = 0; j < 2; j++) bR[j] = *(const float4*)(wp + ((size_t)kt * 16 + 8 * j) * NW);
    };
    auto STS = [&](int s) {
        #pragma unroll
        for (int j = 0; j < 2; j++) {
            uint4 u = { f2tf(aR[j].x), f2tf(aR[j].y), f2tf(aR[j].z), f2tf(aR[j].w) };
            *(uint4*)(&smA[s][a_st[j]]) = u;
        }
        #pragma unroll
        for (int j = 0; j < 2; j++) {
            uint4 u = { f2tf(bR[j].x), f2tf(bR[j].y), f2tf(bR[j].z), f2tf(bR[j].w) };
            *(uint4*)(&smB[s][b_st[j]]) = u;
        }
    };

    float acc[4][4][4] = {};

    LDG(0); STS(0); __syncthreads();

    for (int kt = 0; kt < NK; ++kt) {
        const int cur = kt & 1;
        if (kt + 1 < NK) LDG(kt + 1);
        const uint32_t* A0 = smA[cur];
        const uint32_t* B0 = smB[cur];
        #pragma unroll
        for (int ks = 0; ks < 2; ks++) {
            uint32_t afr[4][4], bfr[4][2];
            #pragma unroll
            for (int mi = 0; mi < 4; mi++) {
                const uint32_t* p = A0 + (uint32_t)(wm * 64 + mi * 16 + qg) * SA + ks * 8 + qt;
                afr[mi][0] = p[0];
                afr[mi][1] = p[8 * SA];
                afr[mi][2] = p[4];
                afr[mi][3] = p[8 * SA + 4];
            }
            #pragma unroll
            for (int ni = 0; ni < 4; ni++) {
                const uint32_t* p = B0 + (uint32_t)(ks * 8 + qt) * SBW + wn * 32 + ni * 8 + qg;
                bfr[ni][0] = p[0];
                bfr[ni][1] = p[4 * SBW];
            }
            #pragma unroll
            for (int mi = 0; mi < 4; mi++)
                #pragma unroll
                for (int ni = 0; ni < 4; ni++)
                    mma8(acc[mi][ni], afr[mi], bfr[ni]);
        }
        if (kt + 1 < NK) STS((kt + 1) & 1);
        __syncthreads();
    }

    // epilogue: c0=(qg,2qt), c1=(qg,2qt+1), c2=(qg+8,2qt), c3=(qg+8,2qt+1)
    #pragma unroll
    for (int mi = 0; mi < 4; mi++) {
        #pragma unroll
        for (int half = 0; half < 2; half++) {
            const int row = m0 + wm * 64 + mi * 16 + qg + half * 8;
            if (row >= count) continue;
            #pragma unroll
            for (int ni = 0; ni < 4; ni++) {
                const int cn = n0 + wn * 32 + ni * 8 + 2 * qt;
                const float c0 = acc[mi][ni][half * 2 + 0];
                const float c1 = acc[mi][ni][half * 2 + 1];
                const float2 bb = *(const float2*)(bias + (size_t)e * NW + cn);
                if (MODE == 1) {
                    float2 v = { c0 + bb.x, c1 + bb.y };
                    *(float2*)(g_Z1 + ((size_t)e * CAP + row) * F_MID + cn) = v;
                } else if (MODE == 3) {
                    const float2 z1 = *(const float2*)(g_Z1 + ((size_t)e * CAP + row) * F_MID + cn);
                    const float s0 = z1.x / (1.0f + __expf(-z1.x));
                    const float s1 = z1.y / (1.0f + __expf(-z1.y));
                    float2 v = { s0 * (c0 + bb.x), s1 * (c1 + bb.y) };
                    *(float2*)(g_H + ((size_t)e * CAP + row) * F_MID + cn) = v;
                } else {
                    const int tok = g_slots[e * CAP + row];
                    float2 v = { c0 + bb.x, c1 + bb.y };
                    *(float2*)(out + (size_t)tok * D_IN + cn) = v;
                }
            }
        }
    }
}

// ---------------------------------------------------------------- launch
extern "C" void kernel_launch(void* const* d_in, const int* in_sizes, int n_in,
                              void* d_out, int out_size) {
    const float* x   = (const float*)d_in[0];
    const float* W1  = (const float*)d_in[1];
    const float* b1  = (const float*)d_in[2];
    const float* W2  = (const float*)d_in[3];
    const float* b2  = (const float*)d_in[4];
    const float* W3  = (const float*)d_in[5];
    const float* b3  = (const float*)d_in[6];
    const int*   idx = (const int*)d_in[7];   // int32 on device (JAX x64 off)
    float* out = (float*)d_out;

    build_slots<<<NEXP, 256>>>(idx);

    dim3 g13(F_MID / 128, CAP / 128, NEXP);   // (8, 4, 32)
    gemm_tc<1><<<g13, 256>>>(x, W1, b1, nullptr);
    gemm_tc<3><<<g13, 256>>>(x, W3, b3, nullptr);

    dim3 g2(D_IN / 128, CAP / 128, NEXP);     // (16, 4, 32)
    gemm_tc<2><<<g2, 256>>>(nullptr, W2, b2, out);
}

// round 6
// speedup vs baseline: 2.4279x; 1.0274x over previous
#include <cuda_runtime.h>
#include <cstdint>

#define D_IN   2048
#define F_MID  1024
#define NEXP   32
#define CAP    512
#define TTOK   8192

#define SA  20u          // A smem row stride (words) - conflict-free for frag reads
#define SBW 132u         // B smem row stride (words)

// fused-kernel smem layout (words per stage): A 128*20=2560, B1 16*132=2112, B3 2112
#define F_STGW  6784u
#define F_SMEM_BYTES (2u * F_STGW * 4u)   // 54272

// scratch (__device__ globals: allocation-free rule)
__device__ int   g_slots[NEXP * CAP];
__device__ int   g_counts[NEXP];
__device__ float g_H[(size_t)NEXP * CAP * F_MID];  // 64 MB

__device__ __forceinline__ uint32_t f2tf(float f) {
    uint32_t u; asm("cvt.rna.tf32.f32 %0, %1;" : "=r"(u) : "f"(f)); return u;
}
__device__ __forceinline__ void mma8(float* c, const uint32_t* a, const uint32_t* b) {
    asm volatile(
        "mma.sync.aligned.m16n8k8.row.col.f32.tf32.tf32.f32 "
        "{%0,%1,%2,%3}, {%4,%5,%6,%7}, {%8,%9}, {%0,%1,%2,%3};"
        : "+f"(c[0]), "+f"(c[1]), "+f"(c[2]), "+f"(c[3])
        : "r"(a[0]), "r"(a[1]), "r"(a[2]), "r"(a[3]), "r"(b[0]), "r"(b[1]));
}

// ---------------------------------------------------------------- dispatch
__global__ void build_slots(const int* __restrict__ idx) {
    const int e = blockIdx.x, tid = threadIdx.x;
    const int lane = tid & 31, w = tid >> 5;
    __shared__ int wsum[8];
    int base = 0;
    for (int start = 0; start < TTOK; start += 256) {
        int t = start + tid;
        bool m = (idx[t] == e);
        unsigned bal = __ballot_sync(0xffffffffu, m);
        if (lane == 0) wsum[w] = __popc(bal);
        __syncthreads();
        int woff = 0, tot = 0;
        #pragma unroll
        for (int i = 0; i < 8; i++) { int v = wsum[i]; tot += v; if (i < w) woff += v; }
        if (m) {
            int pos = base + woff + __popc(bal & ((1u << lane) - 1u));
            if (pos < CAP) g_slots[e * CAP + pos] = t;
        }
        base += tot;
        __syncthreads();
    }
    if (tid == 0) g_counts[e] = base < CAP ? base : CAP;
}

// ---------------------------------------------------------------- fused GEMM1+3
// g_H = silu(gatherX @ W1 + b1) * (gatherX @ W3 + b3)
// CTA 128x128, K-chunk 16, 8 warps (2m x 4n), warp tile 64x32 per B, dual acc.
__global__ __launch_bounds__(256, 1) void gemm13_f(
    const float* __restrict__ x,
    const float* __restrict__ W1, const float* __restrict__ b1,
    const float* __restrict__ W3, const float* __restrict__ b3)
{
    constexpr int NK = D_IN / 16;   // 128

    const int e  = blockIdx.z;
    const int m0 = blockIdx.y * 128;
    const int n0 = blockIdx.x * 128;
    const int count = g_counts[e];
    if (m0 >= count) return;

    extern __shared__ uint32_t sm[];

    const int tid = threadIdx.x, wid = tid >> 5, lane = tid & 31;
    const int wm = wid >> 2, wn = wid & 3;
    const int qg = lane >> 2, qt = lane & 3;

    // A producer: 2 float4 per thread: rows (tid>>2)+{0,64}
    const int ar  = tid >> 2;
    const int ak4 = (tid & 3) * 4;
    const float* ap[2];
    uint32_t a_st[2];
    #pragma unroll
    for (int j = 0; j < 2; j++) {
        const int grow = m0 + ar + 64 * j;
        const int tok = (grow < count) ? g_slots[e * CAP + grow] : 0;
        ap[j]   = x + (size_t)tok * D_IN + ak4;
        a_st[j] = (uint32_t)(ar + 64 * j) * SA + ak4;
    }
    // B producers: 2 float4 per thread per matrix: k-rows (tid>>5)+{0,8}
    const int bkr = tid >> 5;
    const int bn4 = (tid & 31) * 4;
    const float* w1p = W1 + ((size_t)e * D_IN + bkr) * F_MID + n0 + bn4;
    const float* w3p = W3 + ((size_t)e * D_IN + bkr) * F_MID + n0 + bn4;
    const uint32_t b_st[2] = { (uint32_t)bkr * SBW + bn4, (uint32_t)(bkr + 8) * SBW + bn4 };

    float4 aR[2], b1R[2], b3R[2];
    auto LDG = [&](int kt) {
        #pragma unroll
        for (int j = 0; j < 2; j++) aR[j] = *(const float4*)(ap[j] + kt * 16);
        #pragma unroll
        for (int j = 0; j < 2; j++) {
            const size_t ko = ((size_t)kt * 16 + 8 * j) * F_MID;
            b1R[j] = *(const float4*)(w1p + ko);
            b3R[j] = *(const float4*)(w3p + ko);
        }
    };
    auto STS = [&](int s) {
        uint32_t* A0 = sm + s * F_STGW;
        uint32_t* B1 = A0 + 2560;
        uint32_t* B3 = A0 + 4672;
        #pragma unroll
        for (int j = 0; j < 2; j++) {
            uint4 u = { f2tf(aR[j].x), f2tf(aR[j].y), f2tf(aR[j].z), f2tf(aR[j].w) };
            *(uint4*)(A0 + a_st[j]) = u;
        }
        #pragma unroll
        for (int j = 0; j < 2; j++) {
            uint4 u = { f2tf(b1R[j].x), f2tf(b1R[j].y), f2tf(b1R[j].z), f2tf(b1R[j].w) };
            *(uint4*)(B1 + b_st[j]) = u;
            uint4 q = { f2tf(b3R[j].x), f2tf(b3R[j].y), f2tf(b3R[j].z), f2tf(b3R[j].w) };
            *(uint4*)(B3 + b_st[j]) = q;
        }
    };

    float acc1[4][4][4] = {}, acc3[4][4][4] = {};

    LDG(0); STS(0); __syncthreads();

    for (int kt = 0; kt < NK; ++kt) {
        const int cur = kt & 1;
        if (kt + 1 < NK) LDG(kt + 1);
        const uint32_t* A0 = sm + cur * F_STGW;
        const uint32_t* B1 = A0 + 2560;
        const uint32_t* B3 = A0 + 4672;
        #pragma unroll
        for (int ks = 0; ks < 2; ks++) {
            uint32_t afr[4][4], bfr1[4][2], bfr3[4][2];
            #pragma unroll
            for (int mi = 0; mi < 4; mi++) {
                const uint32_t* p = A0 + (uint32_t)(wm * 64 + mi * 16 + qg) * SA + ks * 8 + qt;
                afr[mi][0] = p[0];
                afr[mi][1] = p[8 * SA];
                afr[mi][2] = p[4];
                afr[mi][3] = p[8 * SA + 4];
            }
            #pragma unroll
            for (int ni = 0; ni < 4; ni++) {
                const uint32_t off = (uint32_t)(ks * 8 + qt) * SBW + wn * 32 + ni * 8 + qg;
                bfr1[ni][0] = B1[off];
                bfr1[ni][1] = B1[off + 4 * SBW];
                bfr3[ni][0] = B3[off];
                bfr3[ni][1] = B3[off + 4 * SBW];
            }
            #pragma unroll
            for (int mi = 0; mi < 4; mi++)
                #pragma unroll
                for (int ni = 0; ni < 4; ni++) {
                    mma8(acc1[mi][ni], afr[mi], bfr1[ni]);
                    mma8(acc3[mi][ni], afr[mi], bfr3[ni]);
                }
        }
        if (kt + 1 < NK) STS((kt + 1) & 1);
        __syncthreads();
    }

    // epilogue: SwiGLU -> g_H
    #pragma unroll
    for (int mi = 0; mi < 4; mi++) {
        #pragma unroll
        for (int half = 0; half < 2; half++) {
            const int row = m0 + wm * 64 + mi * 16 + qg + half * 8;
            if (row >= count) continue;
            #pragma unroll
            for (int ni = 0; ni < 4; ni++) {
                const int cn = n0 + wn * 32 + ni * 8 + 2 * qt;
                const float2 bb1 = *(const float2*)(b1 + (size_t)e * F_MID + cn);
                const float2 bb3 = *(const float2*)(b3 + (size_t)e * F_MID + cn);
                const float z10 = acc1[mi][ni][half * 2 + 0] + bb1.x;
                const float z11 = acc1[mi][ni][half * 2 + 1] + bb1.y;
                const float z30 = acc3[mi][ni][half * 2 + 0] + bb3.x;
                const float z31 = acc3[mi][ni][half * 2 + 1] + bb3.y;
                const float s0 = z10 / (1.0f + __expf(-z10));
                const float s1 = z11 / (1.0f + __expf(-z11));
                float2 v = { s0 * z30, s1 * z31 };
                *(float2*)(g_H + ((size_t)e * CAP + row) * F_MID + cn) = v;
            }
        }
    }
}

// ---------------------------------------------------------------- GEMM2 (as R5)
__global__ __launch_bounds__(256, 2) void gemm2_tc(
    const float* __restrict__ W, const float* __restrict__ bias,
    float* __restrict__ out)
{
    constexpr int KD = F_MID, NW = D_IN, NK = KD / 16;

    const int e  = blockIdx.z;
    const int m0 = blockIdx.y * 128;
    const int n0 = blockIdx.x * 128;
    const int count = g_counts[e];
    if (m0 >= count) return;

    __shared__ uint32_t smA[2][128 * SA];
    __shared__ uint32_t smB[2][16 * SBW];

    const int tid = threadIdx.x, wid = tid >> 5, lane = tid & 31;
    const int wm = wid >> 2, wn = wid & 3;
    const int qg = lane >> 2, qt = lane & 3;

    const int ar  = tid >> 2;
    const int ak4 = (tid & 3) * 4;
    const float* ap[2];
    uint32_t a_st[2];
    #pragma unroll
    for (int j = 0; j < 2; j++) {
        const int grow = m0 + ar + 64 * j;
        ap[j]   = g_H + ((size_t)e * CAP + grow) * F_MID + ak4;  // pad rows stay zero
        a_st[j] = (uint32_t)(ar + 64 * j) * SA + ak4;
    }
    const int bkr = tid >> 5;
    const int bn4 = (tid & 31) * 4;
    const float* wp = W + ((size_t)e * KD + bkr) * NW + n0 + bn4;
    const uint32_t b_st[2] = { (uint32_t)bkr * SBW + bn4, (uint32_t)(bkr + 8) * SBW + bn4 };

    float4 aR[2], bR[2];
    auto LDG = [&](int kt) {
        #pragma unroll
        for (int j = 0; j < 2; j++) aR[j] = *(const float4*)(ap[j] + kt * 16);
        #pragma unroll
        for (int j = 0; j < 2; j++) bR[j] = *(const float4*)(wp + ((size_t)kt * 16 + 8 * j) * NW);
    };
    auto STS = [&](int s) {
        #pragma unroll
        for (int j = 0; j < 2; j++) {
            uint4 u = { f2tf(aR[j].x), f2tf(aR[j].y), f2tf(aR[j].z), f2tf(aR[j].w) };
            *(uint4*)(&smA[s][a_st[j]]) = u;
        }
        #pragma unroll
        for (int j = 0; j < 2; j++) {
            uint4 u = { f2tf(bR[j].x), f2tf(bR[j].y), f2tf(bR[j].z), f2tf(bR[j].w) };
            *(uint4*)(&smB[s][b_st[j]]) = u;
        }
    };

    float acc[4][4][4] = {};

    LDG(0); STS(0); __syncthreads();

    for (int kt = 0; kt < NK; ++kt) {
        const int cur = kt & 1;
        if (kt + 1 < NK) LDG(kt + 1);
        const uint32_t* A0 = smA[cur];
        const uint32_t* B0 = smB[cur];
        #pragma unroll
        for (int ks = 0; ks < 2; ks++) {
            uint32_t afr[4][4], bfr[4][2];
            #pragma unroll
            for (int mi = 0; mi < 4; mi++) {
                const uint32_t* p = A0 + (uint32_t)(wm * 64 + mi * 16 + qg) * SA + ks * 8 + qt;
                afr[mi][0] = p[0];
                afr[mi][1] = p[8 * SA];
                afr[mi][2] = p[4];
                afr[mi][3] = p[8 * SA + 4];
            }
            #pragma unroll
            for (int ni = 0; ni < 4; ni++) {
                const uint32_t* p = B0 + (uint32_t)(ks * 8 + qt) * SBW + wn * 32 + ni * 8 + qg;
                bfr[ni][0] = p[0];
                bfr[ni][1] = p[4 * SBW];
            }
            #pragma unroll
            for (int mi = 0; mi < 4; mi++)
                #pragma unroll
                for (int ni = 0; ni < 4; ni++)
                    mma8(acc[mi][ni], afr[mi], bfr[ni]);
        }
        if (kt + 1 < NK) STS((kt + 1) & 1);
        __syncthreads();
    }

    #pragma unroll
    for (int mi = 0; mi < 4; mi++) {
        #pragma unroll
        for (int half = 0; half < 2; half++) {
            const int row = m0 + wm * 64 + mi * 16 + qg + half * 8;
            if (row >= count) continue;
            const int tok = g_slots[e * CAP + row];
            #pragma unroll
            for (int ni = 0; ni < 4; ni++) {
                const int cn = n0 + wn * 32 + ni * 8 + 2 * qt;
                const float2 bb = *(const float2*)(bias + (size_t)e * NW + cn);
                float2 v = { acc[mi][ni][half * 2 + 0] + bb.x,
                             acc[mi][ni][half * 2 + 1] + bb.y };
                *(float2*)(out + (size_t)tok * D_IN + cn) = v;
            }
        }
    }
}

// ---------------------------------------------------------------- launch
extern "C" void kernel_launch(void* const* d_in, const int* in_sizes, int n_in,
                              void* d_out, int out_size) {
    const float* x   = (const float*)d_in[0];
    const float* W1  = (const float*)d_in[1];
    const float* b1  = (const float*)d_in[2];
    const float* W2  = (const float*)d_in[3];
    const float* b2  = (const float*)d_in[4];
    const float* W3  = (const float*)d_in[5];
    const float* b3  = (const float*)d_in[6];
    const int*   idx = (const int*)d_in[7];   // int32 on device (JAX x64 off)
    float* out = (float*)d_out;

    cudaFuncSetAttribute(gemm13_f, cudaFuncAttributeMaxDynamicSharedMemorySize, F_SMEM_BYTES);

    build_slots<<<NEXP, 256>>>(idx);

    dim3 g13(F_MID / 128, CAP / 128, NEXP);   // (8, 4, 32)
    gemm13_f<<<g13, 256, F_SMEM_BYTES>>>(x, W1, b1, W3, b3);

    dim3 g2(D_IN / 128, CAP / 128, NEXP);     // (16, 4, 32)
    gemm2_tc<<<g2, 256>>>(W2, b2, out);
}

// round 7
// speedup vs baseline: 2.5846x; 1.0646x over previous
#include <cuda_runtime.h>
#include <cstdint>

#define D_IN   2048
#define F_MID  1024
#define NEXP   32
#define CAP    512
#define TTOK   8192

#define SA   20u    // A smem row stride (words): conflict-free frag reads
#define SBW  136u   // B smem row stride (words): qt*8+qg all-distinct banks
#define NSTAGE 4

// per-stage words
#define S2W   (128u * SA + 16u * SBW)            // gemm2: 2560 + 2176 = 4736
#define SFW   (128u * SA + 2u * 16u * SBW)       // fused: 2560 + 4352 = 6912
#define SMEM2 (NSTAGE * S2W * 4u)                // 75776 B
#define SMEMF (NSTAGE * SFW * 4u)                // 110592 B

// scratch (__device__ globals: allocation-free rule)
__device__ int   g_slots[NEXP * CAP];
__device__ int   g_counts[NEXP];
__device__ float g_H[(size_t)NEXP * CAP * F_MID];  // 64 MB

__device__ __forceinline__ uint32_t smem_u32(const void* p) {
    uint32_t a;
    asm("{ .reg .u64 t; cvta.to.shared.u64 t, %1; cvt.u32.u64 %0, t; }" : "=r"(a) : "l"(p));
    return a;
}
__device__ __forceinline__ uint32_t f2tf(float f) {
    uint32_t u; asm("cvt.rna.tf32.f32 %0, %1;" : "=r"(u) : "f"(f)); return u;
}
__device__ __forceinline__ uint32_t c2t(uint32_t raw) {   // raw fp32 bits -> tf32 bits
    return f2tf(__uint_as_float(raw));
}
__device__ __forceinline__ void cpa16(uint32_t dst, const float* src) {
    asm volatile("cp.async.cg.shared.global [%0], [%1], 16;" :: "r"(dst), "l"(src) : "memory");
}
__device__ __forceinline__ void cpa_commit() {
    asm volatile("cp.async.commit_group;" ::: "memory");
}
template<int N> __device__ __forceinline__ void cpa_wait() {
    asm volatile("cp.async.wait_group %0;" :: "n"(N) : "memory");
}
__device__ __forceinline__ void mma8(float* c, const uint32_t* a, const uint32_t* b) {
    asm volatile(
        "mma.sync.aligned.m16n8k8.row.col.f32.tf32.tf32.f32 "
        "{%0,%1,%2,%3}, {%4,%5,%6,%7}, {%8,%9}, {%0,%1,%2,%3};"
        : "+f"(c[0]), "+f"(c[1]), "+f"(c[2]), "+f"(c[3])
        : "r"(a[0]), "r"(a[1]), "r"(a[2]), "r"(a[3]), "r"(b[0]), "r"(b[1]));
}

// ---------------------------------------------------------------- dispatch
__global__ void build_slots(const int* __restrict__ idx) {
    const int e = blockIdx.x, tid = threadIdx.x;
    const int lane = tid & 31, w = tid >> 5;
    __shared__ int wsum[8];
    int base = 0;
    for (int start = 0; start < TTOK; start += 256) {
        int t = start + tid;
        bool m = (idx[t] == e);
        unsigned bal = __ballot_sync(0xffffffffu, m);
        if (lane == 0) wsum[w] = __popc(bal);
        __syncthreads();
        int woff = 0, tot = 0;
        #pragma unroll
        for (int i = 0; i < 8; i++) { int v = wsum[i]; tot += v; if (i < w) woff += v; }
        if (m) {
            int pos = base + woff + __popc(bal & ((1u << lane) - 1u));
            if (pos < CAP) g_slots[e * CAP + pos] = t;
        }
        base += tot;
        __syncthreads();
    }
    if (tid == 0) g_counts[e] = base < CAP ? base : CAP;
}

// ---------------------------------------------------------------- fused GEMM1+3
// g_H = silu(gatherX @ W1 + b1) * (gatherX @ W3 + b3)
// CTA 128x128, K-chunk 16, 8 warps (2m x 4n), dual acc, 4-stage cp.async.
__global__ __launch_bounds__(256, 1) void gemm13_f(
    const float* __restrict__ x,
    const float* __restrict__ W1, const float* __restrict__ b1,
    const float* __restrict__ W3, const float* __restrict__ b3)
{
    constexpr int NK = D_IN / 16;   // 128

    const int e  = blockIdx.z;
    const int m0 = blockIdx.y * 128;
    const int n0 = blockIdx.x * 128;
    const int count = g_counts[e];
    if (m0 >= count) return;

    extern __shared__ uint32_t sm[];
    const uint32_t sbase = smem_u32(sm);

    const int tid = threadIdx.x, wid = tid >> 5, lane = tid & 31;
    const int wm = wid >> 2, wn = wid & 3;
    const int qg = lane >> 2, qt = lane & 3;

    // A: rows (tid>>2)+{0,64}, cols (tid&3)*4
    const int ar  = tid >> 2;
    const int ak4 = (tid & 3) * 4;
    const float* ap[2];
    uint32_t a_st[2];
    #pragma unroll
    for (int j = 0; j < 2; j++) {
        const int grow = m0 + ar + 64 * j;
        const int tok = (grow < count) ? g_slots[e * CAP + grow] : 0;
        ap[j]   = x + (size_t)tok * D_IN + ak4;
        a_st[j] = (uint32_t)(ar + 64 * j) * SA + ak4;
    }
    // B: k-rows (tid>>5)+{0,8}, cols (tid&31)*4
    const int bkr = tid >> 5;
    const int bn4 = (tid & 31) * 4;
    const float* w1p = W1 + ((size_t)e * D_IN + bkr) * F_MID + n0 + bn4;
    const float* w3p = W3 + ((size_t)e * D_IN + bkr) * F_MID + n0 + bn4;
    const uint32_t b_st[2] = { (uint32_t)bkr * SBW + bn4, (uint32_t)(bkr + 8) * SBW + bn4 };

    auto issue = [&](int kt) {
        const uint32_t so = (uint32_t)(kt & (NSTAGE - 1)) * SFW;
        #pragma unroll
        for (int j = 0; j < 2; j++)
            cpa16(sbase + (so + a_st[j]) * 4, ap[j] + kt * 16);
        #pragma unroll
        for (int j = 0; j < 2; j++) {
            const size_t ko = ((size_t)kt * 16 + 8 * j) * F_MID;
            cpa16(sbase + (so + 2560 + b_st[j]) * 4, w1p + ko);
            cpa16(sbase + (so + 4736 + b_st[j]) * 4, w3p + ko);
        }
        cpa_commit();
    };

    float acc1[4][4][4] = {}, acc3[4][4][4] = {};

    issue(0); issue(1); issue(2);

    for (int kt = 0; kt < NK; ++kt) {
        cpa_wait<NSTAGE - 2>();
        __syncthreads();
        if (kt + NSTAGE - 1 < NK) issue(kt + NSTAGE - 1);

        const uint32_t* A0 = sm + (uint32_t)(kt & (NSTAGE - 1)) * SFW;
        const uint32_t* B1 = A0 + 2560;
        const uint32_t* B3 = A0 + 4736;
        #pragma unroll
        for (int ks = 0; ks < 2; ks++) {
            uint32_t afr[4][4], bfr1[4][2], bfr3[4][2];
            #pragma unroll
            for (int mi = 0; mi < 4; mi++) {
                const uint32_t* p = A0 + (uint32_t)(wm * 64 + mi * 16 + qg) * SA + ks * 8 + qt;
                afr[mi][0] = c2t(p[0]);
                afr[mi][1] = c2t(p[8 * SA]);
                afr[mi][2] = c2t(p[4]);
                afr[mi][3] = c2t(p[8 * SA + 4]);
            }
            #pragma unroll
            for (int ni = 0; ni < 4; ni++) {
                const uint32_t off = (uint32_t)(ks * 8 + qt) * SBW + wn * 32 + ni * 8 + qg;
                bfr1[ni][0] = c2t(B1[off]);
                bfr1[ni][1] = c2t(B1[off + 4 * SBW]);
                bfr3[ni][0] = c2t(B3[off]);
                bfr3[ni][1] = c2t(B3[off + 4 * SBW]);
            }
            #pragma unroll
            for (int mi = 0; mi < 4; mi++)
                #pragma unroll
                for (int ni = 0; ni < 4; ni++) {
                    mma8(acc1[mi][ni], afr[mi], bfr1[ni]);
                    mma8(acc3[mi][ni], afr[mi], bfr3[ni]);
                }
        }
        __syncthreads();
    }

    // epilogue: SwiGLU -> g_H
    #pragma unroll
    for (int mi = 0; mi < 4; mi++) {
        #pragma unroll
        for (int half = 0; half < 2; half++) {
            const int row = m0 + wm * 64 + mi * 16 + qg + half * 8;
            if (row >= count) continue;
            #pragma unroll
            for (int ni = 0; ni < 4; ni++) {
                const int cn = n0 + wn * 32 + ni * 8 + 2 * qt;
                const float2 bb1 = *(const float2*)(b1 + (size_t)e * F_MID + cn);
                const float2 bb3 = *(const float2*)(b3 + (size_t)e * F_MID + cn);
                const float z10 = acc1[mi][ni][half * 2 + 0] + bb1.x;
                const float z11 = acc1[mi][ni][half * 2 + 1] + bb1.y;
                const float z30 = acc3[mi][ni][half * 2 + 0] + bb3.x;
                const float z31 = acc3[mi][ni][half * 2 + 1] + bb3.y;
                const float s0 = z10 / (1.0f + __expf(-z10));
                const float s1 = z11 / (1.0f + __expf(-z11));
                float2 v = { s0 * z30, s1 * z31 };
                *(float2*)(g_H + ((size_t)e * CAP + row) * F_MID + cn) = v;
            }
        }
    }
}

// ---------------------------------------------------------------- GEMM2
// out[tok] = g_H @ W2 + b2 (scatter). Same skeleton, single acc.
__global__ __launch_bounds__(256, 2) void gemm2_tc(
    const float* __restrict__ W, const float* __restrict__ bias,
    float* __restrict__ out)
{
    constexpr int NW = D_IN;
    constexpr int NK = F_MID / 16;   // 64

    const int e  = blockIdx.z;
    const int m0 = blockIdx.y * 128;
    const int n0 = blockIdx.x * 128;
    const int count = g_counts[e];
    if (m0 >= count) return;

    extern __shared__ uint32_t sm[];
    const uint32_t sbase = smem_u32(sm);

    const int tid = threadIdx.x, wid = tid >> 5, lane = tid & 31;
    const int wm = wid >> 2, wn = wid & 3;
    const int qg = lane >> 2, qt = lane & 3;

    const int ar  = tid >> 2;
    const int ak4 = (tid & 3) * 4;
    const float* ap[2];
    uint32_t a_st[2];
    #pragma unroll
    for (int j = 0; j < 2; j++) {
        const int grow = m0 + ar + 64 * j;       // < CAP always
        ap[j]   = g_H + ((size_t)e * CAP + grow) * F_MID + ak4;
        a_st[j] = (uint32_t)(ar + 64 * j) * SA + ak4;
    }
    const int bkr = tid >> 5;
    const int bn4 = (tid & 31) * 4;
    const float* wp = W + ((size_t)e * F_MID + bkr) * NW + n0 + bn4;
    const uint32_t b_st[2] = { (uint32_t)bkr * SBW + bn4, (uint32_t)(bkr + 8) * SBW + bn4 };

    auto issue = [&](int kt) {
        const uint32_t so = (uint32_t)(kt & (NSTAGE - 1)) * S2W;
        #pragma unroll
        for (int j = 0; j < 2; j++)
            cpa16(sbase + (so + a_st[j]) * 4, ap[j] + kt * 16);
        #pragma unroll
        for (int j = 0; j < 2; j++)
            cpa16(sbase + (so + 2560 + b_st[j]) * 4, wp + ((size_t)kt * 16 + 8 * j) * NW);
        cpa_commit();
    };

    float acc[4][4][4] = {};

    issue(0); issue(1); issue(2);

    for (int kt = 0; kt < NK; ++kt) {
        cpa_wait<NSTAGE - 2>();
        __syncthreads();
        if (kt + NSTAGE - 1 < NK) issue(kt + NSTAGE - 1);

        const uint32_t* A0 = sm + (uint32_t)(kt & (NSTAGE - 1)) * S2W;
        const uint32_t* B0 = A0 + 2560;
        #pragma unroll
        for (int ks = 0; ks < 2; ks++) {
            uint32_t afr[4][4], bfr[4][2];
            #pragma unroll
            for (int mi = 0; mi < 4; mi++) {
                const uint32_t* p = A0 + (uint32_t)(wm * 64 + mi * 16 + qg) * SA + ks * 8 + qt;
                afr[mi][0] = c2t(p[0]);
                afr[mi][1] = c2t(p[8 * SA]);
                afr[mi][2] = c2t(p[4]);
                afr[mi][3] = c2t(p[8 * SA + 4]);
            }
            #pragma unroll
            for (int ni = 0; ni < 4; ni++) {
                const uint32_t off = (uint32_t)(ks * 8 + qt) * SBW + wn * 32 + ni * 8 + qg;
                bfr[ni][0] = c2t(B0[off]);
                bfr[ni][1] = c2t(B0[off + 4 * SBW]);
            }
            #pragma unroll
            for (int mi = 0; mi < 4; mi++)
                #pragma unroll
                for (int ni = 0; ni < 4; ni++)
                    mma8(acc[mi][ni], afr[mi], bfr[ni]);
        }
        __syncthreads();
    }

    #pragma unroll
    for (int mi = 0; mi < 4; mi++) {
        #pragma unroll
        for (int half = 0; half < 2; half++) {
            const int row = m0 + wm * 64 + mi * 16 + qg + half * 8;
            if (row >= count) continue;
            const int tok = g_slots[e * CAP + row];
            #pragma unroll
            for (int ni = 0; ni < 4; ni++) {
                const int cn = n0 + wn * 32 + ni * 8 + 2 * qt;
                const float2 bb = *(const float2*)(bias + (size_t)e * NW + cn);
                float2 v = { acc[mi][ni][half * 2 + 0] + bb.x,
                             acc[mi][ni][half * 2 + 1] + bb.y };
                *(float2*)(out + (size_t)tok * D_IN + cn) = v;
            }
        }
    }
}

// ---------------------------------------------------------------- launch
extern "C" void kernel_launch(void* const* d_in, const int* in_sizes, int n_in,
                              void* d_out, int out_size) {
    const float* x   = (const float*)d_in[0];
    const float* W1  = (const float*)d_in[1];
    const float* b1  = (const float*)d_in[2];
    const float* W2  = (const float*)d_in[3];
    const float* b2  = (const float*)d_in[4];
    const float* W3  = (const float*)d_in[5];
    const float* b3  = (const float*)d_in[6];
    const int*   idx = (const int*)d_in[7];   // int32 on device (JAX x64 off)
    float* out = (float*)d_out;

    cudaFuncSetAttribute(gemm13_f, cudaFuncAttributeMaxDynamicSharedMemorySize, SMEMF);
    cudaFuncSetAttribute(gemm2_tc, cudaFuncAttributeMaxDynamicSharedMemorySize, SMEM2);

    build_slots<<<NEXP, 256>>>(idx);

    dim3 g13(F_MID / 128, CAP / 128, NEXP);   // (8, 4, 32)
    gemm13_f<<<g13, 256, SMEMF>>>(x, W1, b1, W3, b3);

    dim3 g2(D_IN / 128, CAP / 128, NEXP);     // (16, 4, 32)
    gemm2_tc<<<g2, 256, SMEM2>>>(W2, b2, out);
}

// round 10
// speedup vs baseline: 2.6994x; 1.0444x over previous
#include <cuda_runtime.h>
#include <cstdint>

#define D_IN   2048
#define F_MID  1024
#define NEXP   32
#define CAP    512
#define TTOK   8192

#define SA   20u    // A smem row stride (words): conflict-free frag reads
#define SBW  136u   // B smem row stride (words): conflict-free frag reads
#define NSTF 4      // stages, fused kernel
#define NST2 2      // stages, gemm2 (keeps smem <= 48K -> 2 CTA/SM)

// per-stage words
#define S2W   (128u * SA + 16u * SBW)            // gemm2: 2560 + 2176 = 4736
#define SFW   (128u * SA + 2u * 16u * SBW)       // fused: 2560 + 4352 = 6912
#define SMEM2 (NST2 * S2W * 4u)                  // 37888 B  (2 CTAs/SM)
#define SMEMF (NSTF * SFW * 4u)                  // 110592 B (1 CTA/SM)

// scratch (__device__ globals: allocation-free rule)
__device__ int   g_slots[NEXP * CAP];
__device__ int   g_counts[NEXP];
__device__ float g_H[(size_t)NEXP * CAP * F_MID];  // 64 MB

__device__ __forceinline__ uint32_t smem_u32(const void* p) {
    uint32_t a;
    asm("{ .reg .u64 t; cvta.to.shared.u64 t, %1; cvt.u32.u64 %0, t; }" : "=r"(a) : "l"(p));
    return a;
}
__device__ __forceinline__ uint32_t f2tf(float f) {
    uint32_t u; asm("cvt.rna.tf32.f32 %0, %1;" : "=r"(u) : "f"(f)); return u;
}
__device__ __forceinline__ uint32_t c2t(uint32_t raw) {
    return f2tf(__uint_as_float(raw));
}
__device__ __forceinline__ void cpa16(uint32_t dst, const float* src) {
    asm volatile("cp.async.cg.shared.global [%0], [%1], 16;" :: "r"(dst), "l"(src) : "memory");
}
__device__ __forceinline__ void cpa_commit() {
    asm volatile("cp.async.commit_group;" ::: "memory");
}
template<int N> __device__ __forceinline__ void cpa_wait() {
    asm volatile("cp.async.wait_group %0;" :: "n"(N) : "memory");
}
__device__ __forceinline__ void mma8(float* c, const uint32_t* a, const uint32_t* b) {
    asm volatile(
        "mma.sync.aligned.m16n8k8.row.col.f32.tf32.tf32.f32 "
        "{%0,%1,%2,%3}, {%4,%5,%6,%7}, {%8,%9}, {%0,%1,%2,%3};"
        : "+f"(c[0]), "+f"(c[1]), "+f"(c[2]), "+f"(c[3])
        : "r"(a[0]), "r"(a[1]), "r"(a[2]), "r"(a[3]), "r"(b[0]), "r"(b[1]));
}

// ---------------------------------------------------------------- dispatch
__global__ void build_slots(const int* __restrict__ idx) {
    const int e = blockIdx.x, tid = threadIdx.x;
    const int lane = tid & 31, w = tid >> 5;
    __shared__ int wsum[8];
    int base = 0;
    for (int start = 0; start < TTOK; start += 256) {
        int t = start + tid;
        bool m = (idx[t] == e);
        unsigned bal = __ballot_sync(0xffffffffu, m);
        if (lane == 0) wsum[w] = __popc(bal);
        __syncthreads();
        int woff = 0, tot = 0;
        #pragma unroll
        for (int i = 0; i < 8; i++) { int v = wsum[i]; tot += v; if (i < w) woff += v; }
        if (m) {
            int pos = base + woff + __popc(bal & ((1u << lane) - 1u));
            if (pos < CAP) g_slots[e * CAP + pos] = t;
        }
        base += tot;
        __syncthreads();
    }
    if (tid == 0) g_counts[e] = base < CAP ? base : CAP;
}

// ---------------------------------------------------------------- fused GEMM1+3
// g_H = silu(gatherX @ W1 + b1) * (gatherX @ W3 + b3)
// CTA 128x128, K-chunk 16, 8 warps (2m x 4n), dual acc, 4-stage cp.async.
// EXACT tail waits: group kt must be complete before reading stage kt&3.
__global__ __launch_bounds__(256, 1) void gemm13_f(
    const float* __restrict__ x,
    const float* __restrict__ W1, const float* __restrict__ b1,
    const float* __restrict__ W3, const float* __restrict__ b3)
{
    constexpr int NK = D_IN / 16;   // 128

    const int e  = blockIdx.z;
    const int m0 = blockIdx.y * 128;
    const int n0 = blockIdx.x * 128;
    const int count = g_counts[e];
    if (m0 >= count) return;

    extern __shared__ uint32_t sm[];
    const uint32_t sbase = smem_u32(sm);

    const int tid = threadIdx.x, wid = tid >> 5, lane = tid & 31;
    const int wm = wid >> 2, wn = wid & 3;
    const int qg = lane >> 2, qt = lane & 3;

    const int ar  = tid >> 2;
    const int ak4 = (tid & 3) * 4;
    const float* ap[2];
    uint32_t a_st[2];
    #pragma unroll
    for (int j = 0; j < 2; j++) {
        const int grow = m0 + ar + 64 * j;
        const int tok = (grow < count) ? g_slots[e * CAP + grow] : 0;
        ap[j]   = x + (size_t)tok * D_IN + ak4;
        a_st[j] = (uint32_t)(ar + 64 * j) * SA + ak4;
    }
    const int bkr = tid >> 5;
    const int bn4 = (tid & 31) * 4;
    const float* w1p = W1 + ((size_t)e * D_IN + bkr) * F_MID + n0 + bn4;
    const float* w3p = W3 + ((size_t)e * D_IN + bkr) * F_MID + n0 + bn4;
    const uint32_t b_st[2] = { (uint32_t)bkr * SBW + bn4, (uint32_t)(bkr + 8) * SBW + bn4 };

    auto issue = [&](int kt) {
        const uint32_t so = (uint32_t)(kt & (NSTF - 1)) * SFW;
        #pragma unroll
        for (int j = 0; j < 2; j++)
            cpa16(sbase + (so + a_st[j]) * 4, ap[j] + kt * 16);
        #pragma unroll
        for (int j = 0; j < 2; j++) {
            const size_t ko = ((size_t)kt * 16 + 8 * j) * F_MID;
            cpa16(sbase + (so + 2560 + b_st[j]) * 4, w1p + ko);
            cpa16(sbase + (so + 4736 + b_st[j]) * 4, w3p + ko);
        }
        cpa_commit();
    };

    float acc1[4][4][4] = {}, acc3[4][4][4] = {};

    issue(0); issue(1); issue(2);

    for (int kt = 0; kt < NK; ++kt) {
        // committed_max = min(kt+2, NK-1); need pending <= committed_max - kt
        if (kt + 2 < NK)      cpa_wait<2>();
        else if (kt + 1 < NK) cpa_wait<1>();
        else                  cpa_wait<0>();
        __syncthreads();
        if (kt + NSTF - 1 < NK) issue(kt + NSTF - 1);

        const uint32_t* A0 = sm + (uint32_t)(kt & (NSTF - 1)) * SFW;
        const uint32_t* B1 = A0 + 2560;
        const uint32_t* B3 = A0 + 4736;
        #pragma unroll
        for (int ks = 0; ks < 2; ks++) {
            uint32_t afr[4][4], bfr1[4][2], bfr3[4][2];
            #pragma unroll
            for (int mi = 0; mi < 4; mi++) {
                const uint32_t* p = A0 + (uint32_t)(wm * 64 + mi * 16 + qg) * SA + ks * 8 + qt;
                afr[mi][0] = c2t(p[0]);
                afr[mi][1] = c2t(p[8 * SA]);
                afr[mi][2] = c2t(p[4]);
                afr[mi][3] = c2t(p[8 * SA + 4]);
            }
            #pragma unroll
            for (int ni = 0; ni < 4; ni++) {
                const uint32_t off = (uint32_t)(ks * 8 + qt) * SBW + wn * 32 + ni * 8 + qg;
                bfr1[ni][0] = c2t(B1[off]);
                bfr1[ni][1] = c2t(B1[off + 4 * SBW]);
                bfr3[ni][0] = c2t(B3[off]);
                bfr3[ni][1] = c2t(B3[off + 4 * SBW]);
            }
            #pragma unroll
            for (int mi = 0; mi < 4; mi++)
                #pragma unroll
                for (int ni = 0; ni < 4; ni++) {
                    mma8(acc1[mi][ni], afr[mi], bfr1[ni]);
                    mma8(acc3[mi][ni], afr[mi], bfr3[ni]);
                }
        }
        __syncthreads();
    }

    // epilogue: SwiGLU -> g_H
    #pragma unroll
    for (int mi = 0; mi < 4; mi++) {
        #pragma unroll
        for (int half = 0; half < 2; half++) {
            const int row = m0 + wm * 64 + mi * 16 + qg + half * 8;
            if (row >= count) continue;
            #pragma unroll
            for (int ni = 0; ni < 4; ni++) {
                const int cn = n0 + wn * 32 + ni * 8 + 2 * qt;
                const float2 bb1 = *(const float2*)(b1 + (size_t)e * F_MID + cn);
                const float2 bb3 = *(const float2*)(b3 + (size_t)e * F_MID + cn);
                const float z10 = acc1[mi][ni][half * 2 + 0] + bb1.x;
                const float z11 = acc1[mi][ni][half * 2 + 1] + bb1.y;
                const float z30 = acc3[mi][ni][half * 2 + 0] + bb3.x;
                const float z31 = acc3[mi][ni][half * 2 + 1] + bb3.y;
                const float s0 = z10 / (1.0f + __expf(-z10));
                const float s1 = z11 / (1.0f + __expf(-z11));
                float2 v = { s0 * z30, s1 * z31 };
                *(float2*)(g_H + ((size_t)e * CAP + row) * F_MID + cn) = v;
            }
        }
    }
}

// ---------------------------------------------------------------- GEMM2
// out[tok] = g_H @ W2 + b2 (scatter). 2-stage cp.async, <=48K smem -> 2 CTA/SM.
// EXACT tail wait: last iteration must wait<0> (group NK-1 is the stage read).
__global__ __launch_bounds__(256, 2) void gemm2_tc(
    const float* __restrict__ W, const float* __restrict__ bias,
    float* __restrict__ out)
{
    constexpr int NW = D_IN;
    constexpr int NK = F_MID / 16;   // 64

    const int e  = blockIdx.z;
    const int m0 = blockIdx.y * 128;
    const int n0 = blockIdx.x * 128;
    const int count = g_counts[e];
    if (m0 >= count) return;

    extern __shared__ uint32_t sm[];
    const uint32_t sbase = smem_u32(sm);

    const int tid = threadIdx.x, wid = tid >> 5, lane = tid & 31;
    const int wm = wid >> 2, wn = wid & 3;
    const int qg = lane >> 2, qt = lane & 3;

    const int ar  = tid >> 2;
    const int ak4 = (tid & 3) * 4;
    const float* ap[2];
    uint32_t a_st[2];
    #pragma unroll
    for (int j = 0; j < 2; j++) {
        const int grow = m0 + ar + 64 * j;
        ap[j]   = g_H + ((size_t)e * CAP + grow) * F_MID + ak4;
        a_st[j] = (uint32_t)(ar + 64 * j) * SA + ak4;
    }
    const int bkr = tid >> 5;
    const int bn4 = (tid & 31) * 4;
    const float* wp = W + ((size_t)e * F_MID + bkr) * NW + n0 + bn4;
    const uint32_t b_st[2] = { (uint32_t)bkr * SBW + bn4, (uint32_t)(bkr + 8) * SBW + bn4 };

    auto issue = [&](int kt) {
        const uint32_t so = (uint32_t)(kt & (NST2 - 1)) * S2W;
        #pragma unroll
        for (int j = 0; j < 2; j++)
            cpa16(sbase + (so + a_st[j]) * 4, ap[j] + kt * 16);
        #pragma unroll
        for (int j = 0; j < 2; j++)
            cpa16(sbase + (so + 2560 + b_st[j]) * 4, wp + ((size_t)kt * 16 + 8 * j) * NW);
        cpa_commit();
    };

    float acc[4][4][4] = {};

    issue(0); issue(1);

    for (int kt = 0; kt < NK; ++kt) {
        // committed_max = min(kt+1, NK-1); need pending <= committed_max - kt
        if (kt + 1 < NK) cpa_wait<1>();
        else             cpa_wait<0>();
        __syncthreads();

        const uint32_t* A0 = sm + (uint32_t)(kt & (NST2 - 1)) * S2W;
        const uint32_t* B0 = A0 + 2560;
        #pragma unroll
        for (int ks = 0; ks < 2; ks++) {
            uint32_t afr[4][4], bfr[4][2];
            #pragma unroll
            for (int mi = 0; mi < 4; mi++) {
                const uint32_t* p = A0 + (uint32_t)(wm * 64 + mi * 16 + qg) * SA + ks * 8 + qt;
                afr[mi][0] = c2t(p[0]);
                afr[mi][1] = c2t(p[8 * SA]);
                afr[mi][2] = c2t(p[4]);
                afr[mi][3] = c2t(p[8 * SA + 4]);
            }
            #pragma unroll
            for (int ni = 0; ni < 4; ni++) {
                const uint32_t off = (uint32_t)(ks * 8 + qt) * SBW + wn * 32 + ni * 8 + qg;
                bfr[ni][0] = c2t(B0[off]);
                bfr[ni][1] = c2t(B0[off + 4 * SBW]);
            }
            #pragma unroll
            for (int mi = 0; mi < 4; mi++)
                #pragma unroll
                for (int ni = 0; ni < 4; ni++)
                    mma8(acc[mi][ni], afr[mi], bfr[ni]);
        }
        __syncthreads();
        if (kt + NST2 < NK) issue(kt + NST2);
    }

    #pragma unroll
    for (int mi = 0; mi < 4; mi++) {
        #pragma unroll
        for (int half = 0; half < 2; half++) {
            const int row = m0 + wm * 64 + mi * 16 + qg + half * 8;
            if (row >= count) continue;
            const int tok = g_slots[e * CAP + row];
            #pragma unroll
            for (int ni = 0; ni < 4; ni++) {
                const int cn = n0 + wn * 32 + ni * 8 + 2 * qt;
                const float2 bb = *(const float2*)(bias + (size_t)e * NW + cn);
                float2 v = { acc[mi][ni][half * 2 + 0] + bb.x,
                             acc[mi][ni][half * 2 + 1] + bb.y };
                *(float2*)(out + (size_t)tok * D_IN + cn) = v;
            }
        }
    }
}

// ---------------------------------------------------------------- launch
extern "C" void kernel_launch(void* const* d_in, const int* in_sizes, int n_in,
                              void* d_out, int out_size) {
    const float* x   = (const float*)d_in[0];
    const float* W1  = (const float*)d_in[1];
    const float* b1  = (const float*)d_in[2];
    const float* W2  = (const float*)d_in[3];
    const float* b2  = (const float*)d_in[4];
    const float* W3  = (const float*)d_in[5];
    const float* b3  = (const float*)d_in[6];
    const int*   idx = (const int*)d_in[7];   // int32 on device (JAX x64 off)
    float* out = (float*)d_out;

    cudaFuncSetAttribute(gemm13_f, cudaFuncAttributeMaxDynamicSharedMemorySize, SMEMF);
    cudaFuncSetAttribute(gemm2_tc, cudaFuncAttributeMaxDynamicSharedMemorySize, SMEM2);

    build_slots<<<NEXP, 256>>>(idx);

    dim3 g13(F_MID / 128, CAP / 128, NEXP);   // (8, 4, 32)
    gemm13_f<<<g13, 256, SMEMF>>>(x, W1, b1, W3, b3);

    dim3 g2(D_IN / 128, CAP / 128, NEXP);     // (16, 4, 32)
    gemm2_tc<<<g2, 256, SMEM2>>>(W2, b2, out);
}